// round 1
// baseline (speedup 1.0000x reference)
#include <cuda_runtime.h>
#include <math.h>

// ---------------------------------------------------------------------------
// Problem constants
// ---------------------------------------------------------------------------
#define BATCH 2
#define SEQ   2048
#define DMODEL 1024
#define NHEAD 16
#define HDIM  64
#define THD   (NHEAD * HDIM)          // 1024
#define MROWS (BATCH * SEQ)           // 4096
#define QK_COLS (2 * THD)             // 2048
#define GN_EPS 1e-5f

// ---------------------------------------------------------------------------
// Scratch (device globals; no allocations allowed)
// ---------------------------------------------------------------------------
__device__ float g_Q[MROWS * QK_COLS];     // 4096 x 2048
__device__ float g_K[MROWS * QK_COLS];     // 4096 x 2048
__device__ float g_V[MROWS * THD];         // 4096 x 1024
__device__ float g_AttO[MROWS * THD];      // 4096 x 1024 (post-GN attention out)
__device__ float g_cosT[SEQ * 32];
__device__ float g_sinT[SEQ * 32];

// ---------------------------------------------------------------------------
// RoPE tables: cos/sin(t * inv_freq[j]) for j in [0,32)
// ---------------------------------------------------------------------------
__global__ void rope_tables_kernel(float* __restrict__ cosT, float* __restrict__ sinT) {
    int i = blockIdx.x * blockDim.x + threadIdx.x;
    if (i >= SEQ * 32) return;
    int t = i >> 5;
    int j = i & 31;
    double invf = pow(10000.0, -(double)(2 * j) / 64.0);
    float f = (float)t * (float)invf;          // fp32 product (matches reference outer)
    cosT[i] = (float)cos((double)f);
    sinT[i] = (float)sin((double)f);
}

// ---------------------------------------------------------------------------
// In-place RoPE on Q and K (both components, all heads)
// ---------------------------------------------------------------------------
__global__ void rope_kernel(float* __restrict__ Q, float* __restrict__ K,
                            const float* __restrict__ cosT, const float* __restrict__ sinT) {
    int idx = blockIdx.x * blockDim.x + threadIdx.x;   // MROWS * 1024 pair slots
    if (idx >= MROWS * 1024) return;
    int m  = idx >> 10;          // row (b*SEQ + s)
    int p  = idx & 1023;         // pair index within row
    int ch = p >> 5;             // comp*NHEAD + head  (0..31)
    int dl = p & 31;             // dim within half
    int s  = m & (SEQ - 1);
    float c  = cosT[s * 32 + dl];
    float sn = sinT[s * 32 + dl];
    int base = m * QK_COLS + ch * HDIM + dl;
    float qlo = Q[base], qhi = Q[base + 32];
    Q[base]      = qlo * c - qhi * sn;
    Q[base + 32] = qhi * c + qlo * sn;
    float klo = K[base], khi = K[base + 32];
    K[base]      = klo * c - khi * sn;
    K[base + 32] = khi * c + klo * sn;
}

// ---------------------------------------------------------------------------
// SGEMM: C[M,N] = A[M,K] * B[K,N], row-major, M%128==0, N%128==0, K%16==0
// 128x128 tile, BK=16, 256 threads, 8x8 per-thread micro-tile.
// ---------------------------------------------------------------------------
__global__ __launch_bounds__(256) void sgemm_kernel(
    const float* __restrict__ A, const float* __restrict__ B, float* __restrict__ C,
    int M, int N, int K)
{
    __shared__ float As[16][132];   // transposed A tile: As[k][m]
    __shared__ float Bs[16][132];

    const int tid = threadIdx.x;
    const int tx = tid & 15;
    const int ty = tid >> 4;
    const int bx = blockIdx.x;     // N tile
    const int by = blockIdx.y;     // M tile

    float acc[8][8];
#pragma unroll
    for (int i = 0; i < 8; i++)
#pragma unroll
        for (int j = 0; j < 8; j++) acc[i][j] = 0.f;

    const int nTiles = K >> 4;
    for (int kt = 0; kt < nTiles; kt++) {
        // load A tile (128x16), store transposed
#pragma unroll
        for (int q = 0; q < 2; q++) {
            int fi = tid + q * 256;         // 0..511
            int ar = fi >> 2;               // 0..127
            int ac4 = fi & 3;               // 0..3
            float4 av = *(const float4*)&A[(size_t)(by * 128 + ar) * K + kt * 16 + ac4 * 4];
            As[ac4 * 4 + 0][ar] = av.x;
            As[ac4 * 4 + 1][ar] = av.y;
            As[ac4 * 4 + 2][ar] = av.z;
            As[ac4 * 4 + 3][ar] = av.w;
        }
        // load B tile (16x128)
#pragma unroll
        for (int q = 0; q < 2; q++) {
            int fi = tid + q * 256;
            int br = fi >> 5;               // 0..15
            int bc4 = fi & 31;              // 0..31
            float4 bv = *(const float4*)&B[(size_t)(kt * 16 + br) * N + bx * 128 + bc4 * 4];
            *(float4*)&Bs[br][bc4 * 4] = bv;
        }
        __syncthreads();

#pragma unroll
        for (int kk = 0; kk < 16; kk++) {
            float a[8], b[8];
            float4 a0 = *(float4*)&As[kk][ty * 8];
            float4 a1 = *(float4*)&As[kk][ty * 8 + 4];
            float4 b0 = *(float4*)&Bs[kk][tx * 8];
            float4 b1 = *(float4*)&Bs[kk][tx * 8 + 4];
            a[0]=a0.x; a[1]=a0.y; a[2]=a0.z; a[3]=a0.w; a[4]=a1.x; a[5]=a1.y; a[6]=a1.z; a[7]=a1.w;
            b[0]=b0.x; b[1]=b0.y; b[2]=b0.z; b[3]=b0.w; b[4]=b1.x; b[5]=b1.y; b[6]=b1.z; b[7]=b1.w;
#pragma unroll
            for (int i = 0; i < 8; i++)
#pragma unroll
                for (int j = 0; j < 8; j++) acc[i][j] = fmaf(a[i], b[j], acc[i][j]);
        }
        __syncthreads();
    }

#pragma unroll
    for (int i = 0; i < 8; i++) {
        size_t row = (size_t)(by * 128 + ty * 8 + i);
        float4 c0 = make_float4(acc[i][0], acc[i][1], acc[i][2], acc[i][3]);
        float4 c1 = make_float4(acc[i][4], acc[i][5], acc[i][6], acc[i][7]);
        *(float4*)&C[row * N + bx * 128 + tx * 8]     = c0;
        *(float4*)&C[row * N + bx * 128 + tx * 8 + 4] = c1;
    }
}

// ---------------------------------------------------------------------------
// Fused differential flash attention + group-norm epilogue.
// Grid: x = q-tile (32), y = b*NHEAD + h (32). Block: 256 threads (16x16).
// Per CTA: 64 q rows; streams 32 k tiles of 64; computes both attention
// branches (shared V); epilogue does diff, GN over Hd=64, gamma/beta,
// (1 - lambda_init) scale, writes g_AttO.
// ---------------------------------------------------------------------------
#define AT_PAD 68
#define AT_SMEM (6 * 64 * AT_PAD * 4)

__global__ __launch_bounds__(256) void attn_kernel(
    const float* __restrict__ Q, const float* __restrict__ K, const float* __restrict__ V,
    const float* __restrict__ lq1, const float* __restrict__ lk1,
    const float* __restrict__ lq2, const float* __restrict__ lk2,
    const float* __restrict__ lam_init_p,
    const float* __restrict__ gnw, const float* __restrict__ gnb,
    float* __restrict__ Out)
{
    extern __shared__ float sm[];
    float* Q1s = sm;
    float* Q2s = Q1s + 64 * AT_PAD;
    float* K1s = Q2s + 64 * AT_PAD;
    float* K2s = K1s + 64 * AT_PAD;
    float* Vs  = K2s + 64 * AT_PAD;
    float* Ps  = Vs  + 64 * AT_PAD;

    const int tid = threadIdx.x;
    const int tx = tid & 15;
    const int ty = tid >> 4;
    const int qtile = blockIdx.x;
    const int bh = blockIdx.y;
    const int b = bh >> 4;
    const int h = bh & 15;
    const int q0 = qtile * 64;
    const int rowg0 = b * SEQ;          // global row base for this batch
    const float scale = 0.125f;         // Hd^-0.5

    const int c1base = h * HDIM;            // q1/k1 column base
    const int c2base = THD + h * HDIM;      // q2/k2 column base
    const int vbase  = h * HDIM;

    // load Q tiles (once)
#pragma unroll
    for (int q = 0; q < 4; q++) {
        int fi = tid + q * 256;          // 0..1023
        int r = fi >> 4;
        int c4 = fi & 15;
        size_t grow = (size_t)(rowg0 + q0 + r);
        float4 v1 = *(const float4*)&Q[grow * QK_COLS + c1base + c4 * 4];
        float4 v2 = *(const float4*)&Q[grow * QK_COLS + c2base + c4 * 4];
        *(float4*)&Q1s[r * AT_PAD + c4 * 4] = v1;
        *(float4*)&Q2s[r * AT_PAD + c4 * 4] = v2;
    }

    float m1[4], l1[4], m2[4], l2[4];
    float O1[4][4], O2[4][4];
#pragma unroll
    for (int i = 0; i < 4; i++) {
        m1[i] = -1e30f; l1[i] = 0.f; m2[i] = -1e30f; l2[i] = 0.f;
#pragma unroll
        for (int j = 0; j < 4; j++) { O1[i][j] = 0.f; O2[i][j] = 0.f; }
    }

    for (int kt = 0; kt < SEQ / 64; kt++) {
        const int k0 = kt * 64;
        __syncthreads();    // previous tile fully consumed
        // load K1, K2, V tiles
#pragma unroll
        for (int q = 0; q < 4; q++) {
            int fi = tid + q * 256;
            int r = fi >> 4;
            int c4 = fi & 15;
            size_t grow = (size_t)(rowg0 + k0 + r);
            float4 k1v = *(const float4*)&K[grow * QK_COLS + c1base + c4 * 4];
            float4 k2v = *(const float4*)&K[grow * QK_COLS + c2base + c4 * 4];
            float4 vv  = *(const float4*)&V[grow * THD + vbase + c4 * 4];
            *(float4*)&K1s[r * AT_PAD + c4 * 4] = k1v;
            *(float4*)&K2s[r * AT_PAD + c4 * 4] = k2v;
            *(float4*)&Vs [r * AT_PAD + c4 * 4] = vv;
        }
        __syncthreads();

        // ======= branch 1 then branch 2 =======
#pragma unroll
        for (int br = 0; br < 2; br++) {
            const float* Qs = br == 0 ? Q1s : Q2s;
            const float* Ks = br == 0 ? K1s : K2s;
            float* mm = br == 0 ? m1 : m2;
            float* ll = br == 0 ? l1 : l2;
            float (*Oacc)[4] = br == 0 ? O1 : O2;

            float acc[4][4];
#pragma unroll
            for (int i = 0; i < 4; i++)
#pragma unroll
                for (int j = 0; j < 4; j++) acc[i][j] = 0.f;

#pragma unroll
            for (int dk = 0; dk < 64; dk += 4) {
                float4 a[4], bb[4];
#pragma unroll
                for (int i = 0; i < 4; i++) a[i]  = *(const float4*)&Qs[(ty * 4 + i) * AT_PAD + dk];
#pragma unroll
                for (int j = 0; j < 4; j++) bb[j] = *(const float4*)&Ks[(tx * 4 + j) * AT_PAD + dk];
#pragma unroll
                for (int i = 0; i < 4; i++)
#pragma unroll
                    for (int j = 0; j < 4; j++)
                        acc[i][j] += a[i].x * bb[j].x + a[i].y * bb[j].y
                                   + a[i].z * bb[j].z + a[i].w * bb[j].w;
            }

            // online softmax update + write P to smem
#pragma unroll
            for (int i = 0; i < 4; i++) {
                float rm = fmaxf(fmaxf(acc[i][0], acc[i][1]), fmaxf(acc[i][2], acc[i][3]));
#pragma unroll
                for (int off = 8; off >= 1; off >>= 1)
                    rm = fmaxf(rm, __shfl_xor_sync(0xffffffffu, rm, off, 16));
                float m_new = fmaxf(mm[i], rm * scale);
                float corr = __expf(mm[i] - m_new);
                float rsum = 0.f;
#pragma unroll
                for (int j = 0; j < 4; j++) {
                    float p = __expf(acc[i][j] * scale - m_new);
                    Ps[(ty * 4 + i) * AT_PAD + tx * 4 + j] = p;
                    rsum += p;
                }
#pragma unroll
                for (int off = 8; off >= 1; off >>= 1)
                    rsum += __shfl_xor_sync(0xffffffffu, rsum, off, 16);
                ll[i] = ll[i] * corr + rsum;
                mm[i] = m_new;
#pragma unroll
                for (int j = 0; j < 4; j++) Oacc[i][j] *= corr;
            }
            __syncthreads();

            // O += P @ V
#pragma unroll
            for (int kk = 0; kk < 64; kk += 4) {
                float4 p[4], vr[4];
#pragma unroll
                for (int i = 0; i < 4; i++) p[i] = *(const float4*)&Ps[(ty * 4 + i) * AT_PAD + kk];
#pragma unroll
                for (int u = 0; u < 4; u++) vr[u] = *(const float4*)&Vs[(kk + u) * AT_PAD + tx * 4];
#pragma unroll
                for (int i = 0; i < 4; i++) {
                    Oacc[i][0] += p[i].x * vr[0].x + p[i].y * vr[1].x + p[i].z * vr[2].x + p[i].w * vr[3].x;
                    Oacc[i][1] += p[i].x * vr[0].y + p[i].y * vr[1].y + p[i].z * vr[2].y + p[i].w * vr[3].y;
                    Oacc[i][2] += p[i].x * vr[0].z + p[i].y * vr[1].z + p[i].z * vr[2].z + p[i].w * vr[3].z;
                    Oacc[i][3] += p[i].x * vr[0].w + p[i].y * vr[1].w + p[i].z * vr[2].w + p[i].w * vr[3].w;
                }
            }
            __syncthreads();   // Ps free for next branch / next tile
        }
    }

    // ======= epilogue: diff + group-norm + scale =======
    const float lam_init = lam_init_p[0];
    const float lam = __expf(lq1[h] * lk1[h]) - __expf(lq2[h] * lk2[h]) + lam_init;
    const float out_scale = 1.0f - lam_init;

    float4 gw = *(const float4*)&gnw[h * HDIM + tx * 4];
    float4 gb = *(const float4*)&gnb[h * HDIM + tx * 4];
    float gwa[4] = {gw.x, gw.y, gw.z, gw.w};
    float gba[4] = {gb.x, gb.y, gb.z, gb.w};

#pragma unroll
    for (int i = 0; i < 4; i++) {
        float inv1 = 1.0f / l1[i];
        float inv2 = lam / l2[i];
        float vals[4];
        float s = 0.f, sq = 0.f;
#pragma unroll
        for (int j = 0; j < 4; j++) {
            float v = O1[i][j] * inv1 - O2[i][j] * inv2;
            vals[j] = v;
            s += v;
            sq += v * v;
        }
#pragma unroll
        for (int off = 8; off >= 1; off >>= 1) {
            s  += __shfl_xor_sync(0xffffffffu, s, off, 16);
            sq += __shfl_xor_sync(0xffffffffu, sq, off, 16);
        }
        float mean = s * (1.0f / 64.0f);
        float var = sq * (1.0f / 64.0f) - mean * mean;
        float inv_std = rsqrtf(var + GN_EPS);
        float4 o;
        o.x = ((vals[0] - mean) * inv_std * gwa[0] + gba[0]) * out_scale;
        o.y = ((vals[1] - mean) * inv_std * gwa[1] + gba[1]) * out_scale;
        o.z = ((vals[2] - mean) * inv_std * gwa[2] + gba[2]) * out_scale;
        o.w = ((vals[3] - mean) * inv_std * gwa[3] + gba[3]) * out_scale;
        size_t grow = (size_t)(rowg0 + q0 + ty * 4 + i);
        *(float4*)&Out[grow * THD + h * HDIM + tx * 4] = o;
    }
}

// ---------------------------------------------------------------------------
// kernel_launch
// ---------------------------------------------------------------------------
extern "C" void kernel_launch(void* const* d_in, const int* in_sizes, int n_in,
                              void* d_out, int out_size)
{
    const float* x   = (const float*)d_in[0];
    const float* Wq  = (const float*)d_in[1];
    const float* Wk  = (const float*)d_in[2];
    const float* Wv  = (const float*)d_in[3];
    const float* Wo  = (const float*)d_in[4];
    const float* lq1 = (const float*)d_in[5];
    const float* lk1 = (const float*)d_in[6];
    const float* lq2 = (const float*)d_in[7];
    const float* lk2 = (const float*)d_in[8];
    const float* lam = (const float*)d_in[9];
    const float* gnw = (const float*)d_in[10];
    const float* gnb = (const float*)d_in[11];
    float* out = (float*)d_out;

    float *Q, *K, *V, *A, *cosT, *sinT;
    cudaGetSymbolAddress((void**)&Q, g_Q);
    cudaGetSymbolAddress((void**)&K, g_K);
    cudaGetSymbolAddress((void**)&V, g_V);
    cudaGetSymbolAddress((void**)&A, g_AttO);
    cudaGetSymbolAddress((void**)&cosT, g_cosT);
    cudaGetSymbolAddress((void**)&sinT, g_sinT);

    cudaFuncSetAttribute(attn_kernel, cudaFuncAttributeMaxDynamicSharedMemorySize, AT_SMEM);

    // RoPE tables
    rope_tables_kernel<<<(SEQ * 32 + 255) / 256, 256>>>(cosT, sinT);

    // Projections
    sgemm_kernel<<<dim3(QK_COLS / 128, MROWS / 128), 256>>>(x, Wq, Q, MROWS, QK_COLS, DMODEL);
    sgemm_kernel<<<dim3(QK_COLS / 128, MROWS / 128), 256>>>(x, Wk, K, MROWS, QK_COLS, DMODEL);
    sgemm_kernel<<<dim3(THD / 128, MROWS / 128), 256>>>(x, Wv, V, MROWS, THD, DMODEL);

    // RoPE (in place on Q, K)
    rope_kernel<<<(MROWS * 1024) / 256, 256>>>(Q, K, cosT, sinT);

    // Differential attention + GN
    attn_kernel<<<dim3(SEQ / 64, BATCH * NHEAD), 256, AT_SMEM>>>(
        Q, K, V, lq1, lk1, lq2, lk2, lam, gnw, gnb, A);

    // Output projection
    sgemm_kernel<<<dim3(DMODEL / 128, MROWS / 128), 256>>>(A, Wo, out, MROWS, DMODEL, DMODEL);
}

// round 2
// speedup vs baseline: 2.3303x; 2.3303x over previous
#include <cuda_runtime.h>
#include <math.h>

// ---------------------------------------------------------------------------
// Problem constants
// ---------------------------------------------------------------------------
#define BATCH 2
#define SEQ   2048
#define DMODEL 1024
#define NHEAD 16
#define HDIM  64
#define THD   (NHEAD * HDIM)          // 1024
#define MROWS (BATCH * SEQ)           // 4096
#define QK_COLS (2 * THD)             // 2048
#define GN_EPS 1e-5f

// ---------------------------------------------------------------------------
// Scratch (device globals; no allocations allowed)
// ---------------------------------------------------------------------------
__device__ float g_Q[MROWS * QK_COLS];     // 4096 x 2048
__device__ float g_K[MROWS * QK_COLS];     // 4096 x 2048
__device__ float g_V[MROWS * THD];         // 4096 x 1024
__device__ float g_Vt[BATCH * NHEAD * HDIM * SEQ];   // [bh][d][s]
__device__ float g_AttO[MROWS * THD];      // 4096 x 1024 (post-GN attention out)
__device__ float g_cosT[SEQ * 32];
__device__ float g_sinT[SEQ * 32];

// ---------------------------------------------------------------------------
// Helpers
// ---------------------------------------------------------------------------
__device__ __forceinline__ unsigned f2tf(float x) {
    unsigned u;
    asm("cvt.rna.tf32.f32 %0, %1;" : "=r"(u) : "f"(x));
    return u;
}

__device__ __forceinline__ void ldsm4(unsigned &r0, unsigned &r1, unsigned &r2, unsigned &r3, unsigned addr) {
    asm volatile("ldmatrix.sync.aligned.m8n8.x4.shared.b16 {%0,%1,%2,%3}, [%4];"
        : "=r"(r0), "=r"(r1), "=r"(r2), "=r"(r3) : "r"(addr));
}

__device__ __forceinline__ void mma8(float* c, const unsigned* a, unsigned b0, unsigned b1) {
    asm volatile(
        "mma.sync.aligned.m16n8k8.row.col.f32.tf32.tf32.f32 "
        "{%0,%1,%2,%3},{%4,%5,%6,%7},{%8,%9},{%0,%1,%2,%3};"
        : "+f"(c[0]), "+f"(c[1]), "+f"(c[2]), "+f"(c[3])
        : "r"(a[0]), "r"(a[1]), "r"(a[2]), "r"(a[3]), "r"(b0), "r"(b1));
}

__device__ __forceinline__ void cp16(unsigned saddr, const void* g) {
    asm volatile("cp.async.cg.shared.global [%0], [%1], 16;" :: "r"(saddr), "l"(g));
}

// ---------------------------------------------------------------------------
// RoPE tables
// ---------------------------------------------------------------------------
__global__ void rope_tables_kernel(float* __restrict__ cosT, float* __restrict__ sinT) {
    int i = blockIdx.x * blockDim.x + threadIdx.x;
    if (i >= SEQ * 32) return;
    int t = i >> 5;
    int j = i & 31;
    double invf = pow(10000.0, -(double)(2 * j) / 64.0);
    float f = (float)t * (float)invf;
    cosT[i] = (float)cos((double)f);
    sinT[i] = (float)sin((double)f);
}

// ---------------------------------------------------------------------------
// In-place RoPE on Q and K; rounds results to tf32 (rna) for unbiased HMMA.
// ---------------------------------------------------------------------------
__global__ void rope_kernel(float* __restrict__ Q, float* __restrict__ K,
                            const float* __restrict__ cosT, const float* __restrict__ sinT) {
    int idx = blockIdx.x * blockDim.x + threadIdx.x;
    if (idx >= MROWS * 1024) return;
    int m  = idx >> 10;
    int p  = idx & 1023;
    int ch = p >> 5;
    int dl = p & 31;
    int s  = m & (SEQ - 1);
    float c  = cosT[s * 32 + dl];
    float sn = sinT[s * 32 + dl];
    int base = m * QK_COLS + ch * HDIM + dl;
    float qlo = Q[base], qhi = Q[base + 32];
    Q[base]      = __uint_as_float(f2tf(qlo * c - qhi * sn));
    Q[base + 32] = __uint_as_float(f2tf(qhi * c + qlo * sn));
    float klo = K[base], khi = K[base + 32];
    K[base]      = __uint_as_float(f2tf(klo * c - khi * sn));
    K[base + 32] = __uint_as_float(f2tf(khi * c + klo * sn));
}

// ---------------------------------------------------------------------------
// V transpose: g_V [b*S+s][h*64+d] -> g_Vt [(b*16+h)*64+d][s], tf32-rounded.
// ---------------------------------------------------------------------------
__global__ void vtrans_kernel(const float* __restrict__ V, float* __restrict__ Vt) {
    __shared__ float t[32][33];
    int bh = blockIdx.z;
    int b = bh >> 4, h = bh & 15;
    int s0 = blockIdx.x * 32, d0 = blockIdx.y * 32;
    int tx = threadIdx.x, ty = threadIdx.y;
#pragma unroll
    for (int j = 0; j < 32; j += 8)
        t[ty + j][tx] = V[(size_t)(b * SEQ + s0 + ty + j) * THD + h * HDIM + d0 + tx];
    __syncthreads();
#pragma unroll
    for (int j = 0; j < 32; j += 8)
        Vt[(size_t)(bh * HDIM + d0 + ty + j) * SEQ + s0 + tx] =
            __uint_as_float(f2tf(t[tx][ty + j]));
}

// ---------------------------------------------------------------------------
// SGEMM: C[M,N] = A[M,K] * B[K,N] (fp32 FFMA path, unchanged)
// ---------------------------------------------------------------------------
__global__ __launch_bounds__(256) void sgemm_kernel(
    const float* __restrict__ A, const float* __restrict__ B, float* __restrict__ C,
    int M, int N, int K)
{
    __shared__ float As[16][132];
    __shared__ float Bs[16][132];

    const int tid = threadIdx.x;
    const int tx = tid & 15;
    const int ty = tid >> 4;
    const int bx = blockIdx.x;
    const int by = blockIdx.y;

    float acc[8][8];
#pragma unroll
    for (int i = 0; i < 8; i++)
#pragma unroll
        for (int j = 0; j < 8; j++) acc[i][j] = 0.f;

    const int nTiles = K >> 4;
    for (int kt = 0; kt < nTiles; kt++) {
#pragma unroll
        for (int q = 0; q < 2; q++) {
            int fi = tid + q * 256;
            int ar = fi >> 2;
            int ac4 = fi & 3;
            float4 av = *(const float4*)&A[(size_t)(by * 128 + ar) * K + kt * 16 + ac4 * 4];
            As[ac4 * 4 + 0][ar] = av.x;
            As[ac4 * 4 + 1][ar] = av.y;
            As[ac4 * 4 + 2][ar] = av.z;
            As[ac4 * 4 + 3][ar] = av.w;
        }
#pragma unroll
        for (int q = 0; q < 2; q++) {
            int fi = tid + q * 256;
            int br = fi >> 5;
            int bc4 = fi & 31;
            float4 bv = *(const float4*)&B[(size_t)(kt * 16 + br) * N + bx * 128 + bc4 * 4];
            *(float4*)&Bs[br][bc4 * 4] = bv;
        }
        __syncthreads();

#pragma unroll
        for (int kk = 0; kk < 16; kk++) {
            float a[8], b[8];
            float4 a0 = *(float4*)&As[kk][ty * 8];
            float4 a1 = *(float4*)&As[kk][ty * 8 + 4];
            float4 b0 = *(float4*)&Bs[kk][tx * 8];
            float4 b1 = *(float4*)&Bs[kk][tx * 8 + 4];
            a[0]=a0.x; a[1]=a0.y; a[2]=a0.z; a[3]=a0.w; a[4]=a1.x; a[5]=a1.y; a[6]=a1.z; a[7]=a1.w;
            b[0]=b0.x; b[1]=b0.y; b[2]=b0.z; b[3]=b0.w; b[4]=b1.x; b[5]=b1.y; b[6]=b1.z; b[7]=b1.w;
#pragma unroll
            for (int i = 0; i < 8; i++)
#pragma unroll
                for (int j = 0; j < 8; j++) acc[i][j] = fmaf(a[i], b[j], acc[i][j]);
        }
        __syncthreads();
    }

#pragma unroll
    for (int i = 0; i < 8; i++) {
        size_t row = (size_t)(by * 128 + ty * 8 + i);
        float4 c0 = make_float4(acc[i][0], acc[i][1], acc[i][2], acc[i][3]);
        float4 c1 = make_float4(acc[i][4], acc[i][5], acc[i][6], acc[i][7]);
        *(float4*)&C[row * N + bx * 128 + tx * 8]     = c0;
        *(float4*)&C[row * N + bx * 128 + tx * 8 + 4] = c1;
    }
}

// ---------------------------------------------------------------------------
// Tensor-core differential flash attention + fused group-norm epilogue.
// Grid: (S/64, B*H). Block: 128 threads (4 warps x 16 q rows).
// mma.sync m16n8k8 tf32 for both QK^T and PV; P round-trips via smem.
// ---------------------------------------------------------------------------
#define ATS 68
#define ATT_SMEM (6 * 64 * ATS * 4)

__global__ __launch_bounds__(128) void attn_tc_kernel(
    const float* __restrict__ Q, const float* __restrict__ K, const float* __restrict__ Vt,
    const float* __restrict__ lq1, const float* __restrict__ lk1,
    const float* __restrict__ lq2, const float* __restrict__ lk2,
    const float* __restrict__ lam_init_p,
    const float* __restrict__ gnw, const float* __restrict__ gnb,
    float* __restrict__ Out)
{
    extern __shared__ float sm[];
    float* Q1s = sm;
    float* Q2s = Q1s + 64 * ATS;
    float* K1s = Q2s + 64 * ATS;
    float* K2s = K1s + 64 * ATS;
    float* Vts = K2s + 64 * ATS;
    float* Ps  = Vts + 64 * ATS;

    const int tid = threadIdx.x;
    const int wid = tid >> 5;
    const int lane = tid & 31;
    const int g = lane >> 2;
    const int tig = lane & 3;
    const int bh = blockIdx.y;
    const int b = bh >> 4;
    const int h = bh & 15;
    const int q0 = blockIdx.x * 64;
    const int rowg0 = b * SEQ;
    const float scale = 0.125f;

    const unsigned smQ1 = (unsigned)__cvta_generic_to_shared(Q1s);
    const unsigned smQ2 = (unsigned)__cvta_generic_to_shared(Q2s);
    const unsigned smK1 = (unsigned)__cvta_generic_to_shared(K1s);
    const unsigned smK2 = (unsigned)__cvta_generic_to_shared(K2s);
    const unsigned smVt = (unsigned)__cvta_generic_to_shared(Vts);
    const unsigned smPs = (unsigned)__cvta_generic_to_shared(Ps);

    // async Q tile loads (64 rows x 64 cols, both components)
#pragma unroll
    for (int q = 0; q < 8; q++) {
        int fi = tid + q * 128;
        int r = fi >> 4, c4 = fi & 15;
        const float* gq = &Q[(size_t)(rowg0 + q0 + r) * QK_COLS + h * HDIM + c4 * 4];
        cp16(smQ1 + (r * ATS + c4 * 4) * 4, gq);
        cp16(smQ2 + (r * ATS + c4 * 4) * 4, gq + THD);
    }
    asm volatile("cp.async.commit_group;");

    float O1[8][4], O2[8][4];
#pragma unroll
    for (int i = 0; i < 8; i++)
#pragma unroll
        for (int j = 0; j < 4; j++) { O1[i][j] = 0.f; O2[i][j] = 0.f; }
    float m1[2] = {-1e30f, -1e30f}, m2[2] = {-1e30f, -1e30f};
    float l1[2] = {0.f, 0.f},       l2[2] = {0.f, 0.f};

    // per-lane ldmatrix base addresses (bytes)
    const unsigned aoffA = ((wid * 16 + (lane & 15)) * ATS + ((lane >> 4) << 2)) * 4;
    const unsigned aQ1 = smQ1 + aoffA;
    const unsigned aQ2 = smQ2 + aoffA;
    const unsigned aPs = smPs + aoffA;
    const unsigned boffB = ((lane & 7) * ATS + ((lane >> 3) << 2)) * 4;
    const unsigned bK1 = smK1 + boffB;
    const unsigned bK2 = smK2 + boffB;
    const unsigned bVt = smVt + boffB;

    for (int kt = 0; kt < SEQ / 64; kt++) {
        const int k0 = kt * 64;
        __syncthreads();   // previous tile fully consumed
#pragma unroll
        for (int q = 0; q < 8; q++) {
            int fi = tid + q * 128;
            int r = fi >> 4, c4 = fi & 15;
            const float* gk = &K[(size_t)(rowg0 + k0 + r) * QK_COLS + h * HDIM + c4 * 4];
            cp16(smK1 + (r * ATS + c4 * 4) * 4, gk);
            cp16(smK2 + (r * ATS + c4 * 4) * 4, gk + THD);
            const float* gv = &Vt[(size_t)(bh * HDIM + r) * SEQ + k0 + c4 * 4];
            cp16(smVt + (r * ATS + c4 * 4) * 4, gv);
        }
        asm volatile("cp.async.commit_group;");
        asm volatile("cp.async.wait_group 0;");
        __syncthreads();

#pragma unroll
        for (int br = 0; br < 2; br++) {
            const unsigned aQ = br ? aQ2 : aQ1;
            const unsigned bK = br ? bK2 : bK1;
            float (*O)[4] = br ? O2 : O1;
            float* mm = br ? m2 : m1;
            float* ll = br ? l2 : l1;

            float S[8][4];
#pragma unroll
            for (int i = 0; i < 8; i++)
#pragma unroll
                for (int j = 0; j < 4; j++) S[i][j] = 0.f;

            // S = Q_w (16x64) @ K^T (64x64)
#pragma unroll
            for (int p = 0; p < 4; p++) {
                unsigned A0[4], A1[4];
                ldsm4(A0[0], A0[1], A0[2], A0[3], aQ + p * 64);
                ldsm4(A1[0], A1[1], A1[2], A1[3], aQ + p * 64 + 32);
#pragma unroll
                for (int nf = 0; nf < 8; nf++) {
                    unsigned Bf[4];
                    ldsm4(Bf[0], Bf[1], Bf[2], Bf[3], bK + nf * (8 * ATS * 4) + p * 64);
                    mma8(S[nf], A0, Bf[0], Bf[1]);
                    mma8(S[nf], A1, Bf[2], Bf[3]);
                }
            }

            // online softmax (rows g and g+8 of this warp's 16-row block)
            float mx0 = -1e30f, mx1 = -1e30f;
#pragma unroll
            for (int nf = 0; nf < 8; nf++) {
                mx0 = fmaxf(mx0, fmaxf(S[nf][0], S[nf][1]));
                mx1 = fmaxf(mx1, fmaxf(S[nf][2], S[nf][3]));
            }
            mx0 = fmaxf(mx0, __shfl_xor_sync(0xffffffffu, mx0, 1));
            mx0 = fmaxf(mx0, __shfl_xor_sync(0xffffffffu, mx0, 2));
            mx1 = fmaxf(mx1, __shfl_xor_sync(0xffffffffu, mx1, 1));
            mx1 = fmaxf(mx1, __shfl_xor_sync(0xffffffffu, mx1, 2));
            float mn0 = fmaxf(mm[0], mx0 * scale);
            float mn1 = fmaxf(mm[1], mx1 * scale);
            float c0 = __expf(mm[0] - mn0);
            float c1 = __expf(mm[1] - mn1);
            float s0 = 0.f, s1 = 0.f;
            const int prow0 = (wid * 16 + g) * ATS + 2 * tig;
#pragma unroll
            for (int nf = 0; nf < 8; nf++) {
                float p00 = __expf(S[nf][0] * scale - mn0);
                float p01 = __expf(S[nf][1] * scale - mn0);
                float p10 = __expf(S[nf][2] * scale - mn1);
                float p11 = __expf(S[nf][3] * scale - mn1);
                s0 += p00 + p01;
                s1 += p10 + p11;
                float2 v0 = make_float2(__uint_as_float(f2tf(p00)), __uint_as_float(f2tf(p01)));
                float2 v1 = make_float2(__uint_as_float(f2tf(p10)), __uint_as_float(f2tf(p11)));
                *(float2*)&Ps[prow0 + nf * 8] = v0;
                *(float2*)&Ps[prow0 + 8 * ATS + nf * 8] = v1;
            }
            s0 += __shfl_xor_sync(0xffffffffu, s0, 1);
            s0 += __shfl_xor_sync(0xffffffffu, s0, 2);
            s1 += __shfl_xor_sync(0xffffffffu, s1, 1);
            s1 += __shfl_xor_sync(0xffffffffu, s1, 2);
            ll[0] = ll[0] * c0 + s0;
            ll[1] = ll[1] * c1 + s1;
            mm[0] = mn0;
            mm[1] = mn1;
#pragma unroll
            for (int nf = 0; nf < 8; nf++) {
                O[nf][0] *= c0; O[nf][1] *= c0;
                O[nf][2] *= c1; O[nf][3] *= c1;
            }
            __syncwarp();

            // O += P (16x64) @ V (64x64)
#pragma unroll
            for (int p = 0; p < 4; p++) {
                unsigned A0[4], A1[4];
                ldsm4(A0[0], A0[1], A0[2], A0[3], aPs + p * 64);
                ldsm4(A1[0], A1[1], A1[2], A1[3], aPs + p * 64 + 32);
#pragma unroll
                for (int df = 0; df < 8; df++) {
                    unsigned Bf[4];
                    ldsm4(Bf[0], Bf[1], Bf[2], Bf[3], bVt + df * (8 * ATS * 4) + p * 64);
                    mma8(O[df], A0, Bf[0], Bf[1]);
                    mma8(O[df], A1, Bf[2], Bf[3]);
                }
            }
            __syncwarp();   // Ps consumed; next branch may overwrite
        }
    }

    // ======= epilogue: diff + group-norm + scale =======
    const float lam_init = lam_init_p[0];
    const float lam = __expf(lq1[h] * lk1[h]) - __expf(lq2[h] * lk2[h]) + lam_init;
    const float osc = 1.0f - lam_init;

#pragma unroll
    for (int r = 0; r < 2; r++) {
        float inv1 = 1.0f / l1[r];
        float inv2 = lam / l2[r];
        float v[16];
        float s = 0.f, sq = 0.f;
#pragma unroll
        for (int nf = 0; nf < 8; nf++) {
            float a0 = O1[nf][2 * r + 0] * inv1 - O2[nf][2 * r + 0] * inv2;
            float a1 = O1[nf][2 * r + 1] * inv1 - O2[nf][2 * r + 1] * inv2;
            v[2 * nf] = a0; v[2 * nf + 1] = a1;
            s += a0 + a1;
            sq += a0 * a0 + a1 * a1;
        }
        s  += __shfl_xor_sync(0xffffffffu, s, 1);
        s  += __shfl_xor_sync(0xffffffffu, s, 2);
        sq += __shfl_xor_sync(0xffffffffu, sq, 1);
        sq += __shfl_xor_sync(0xffffffffu, sq, 2);
        float mean = s * (1.0f / 64.0f);
        float var = sq * (1.0f / 64.0f) - mean * mean;
        float istd = rsqrtf(var + GN_EPS);
        size_t row = (size_t)(rowg0 + q0 + wid * 16 + g + 8 * r);
#pragma unroll
        for (int nf = 0; nf < 8; nf++) {
            int col = h * HDIM + nf * 8 + 2 * tig;
            float gw0 = gnw[col], gw1 = gnw[col + 1];
            float gb0 = gnb[col], gb1 = gnb[col + 1];
            float2 o = make_float2(((v[2 * nf]     - mean) * istd * gw0 + gb0) * osc,
                                   ((v[2 * nf + 1] - mean) * istd * gw1 + gb1) * osc);
            *(float2*)&Out[row * THD + col] = o;
        }
    }
}

// ---------------------------------------------------------------------------
// kernel_launch
// ---------------------------------------------------------------------------
extern "C" void kernel_launch(void* const* d_in, const int* in_sizes, int n_in,
                              void* d_out, int out_size)
{
    const float* x   = (const float*)d_in[0];
    const float* Wq  = (const float*)d_in[1];
    const float* Wk  = (const float*)d_in[2];
    const float* Wv  = (const float*)d_in[3];
    const float* Wo  = (const float*)d_in[4];
    const float* lq1 = (const float*)d_in[5];
    const float* lk1 = (const float*)d_in[6];
    const float* lq2 = (const float*)d_in[7];
    const float* lk2 = (const float*)d_in[8];
    const float* lam = (const float*)d_in[9];
    const float* gnw = (const float*)d_in[10];
    const float* gnb = (const float*)d_in[11];
    float* out = (float*)d_out;

    float *Q, *K, *V, *Vt, *A, *cosT, *sinT;
    cudaGetSymbolAddress((void**)&Q, g_Q);
    cudaGetSymbolAddress((void**)&K, g_K);
    cudaGetSymbolAddress((void**)&V, g_V);
    cudaGetSymbolAddress((void**)&Vt, g_Vt);
    cudaGetSymbolAddress((void**)&A, g_AttO);
    cudaGetSymbolAddress((void**)&cosT, g_cosT);
    cudaGetSymbolAddress((void**)&sinT, g_sinT);

    cudaFuncSetAttribute(attn_tc_kernel, cudaFuncAttributeMaxDynamicSharedMemorySize, ATT_SMEM);

    // RoPE tables
    rope_tables_kernel<<<(SEQ * 32 + 255) / 256, 256>>>(cosT, sinT);

    // Projections (fp32)
    sgemm_kernel<<<dim3(QK_COLS / 128, MROWS / 128), 256>>>(x, Wq, Q, MROWS, QK_COLS, DMODEL);
    sgemm_kernel<<<dim3(QK_COLS / 128, MROWS / 128), 256>>>(x, Wk, K, MROWS, QK_COLS, DMODEL);
    sgemm_kernel<<<dim3(THD / 128, MROWS / 128), 256>>>(x, Wv, V, MROWS, THD, DMODEL);

    // RoPE (in place, tf32-rounded outputs)
    rope_kernel<<<(MROWS * 1024) / 256, 256>>>(Q, K, cosT, sinT);

    // V transpose -> [bh][d][s], tf32-rounded
    vtrans_kernel<<<dim3(SEQ / 32, HDIM / 32, BATCH * NHEAD), dim3(32, 8)>>>(V, Vt);

    // Tensor-core differential attention + GN
    attn_tc_kernel<<<dim3(SEQ / 64, BATCH * NHEAD), 128, ATT_SMEM>>>(
        Q, K, Vt, lq1, lk1, lq2, lk2, lam, gnw, gnb, A);

    // Output projection (fp32)
    sgemm_kernel<<<dim3(DMODEL / 128, MROWS / 128), 256>>>(A, Wo, out, MROWS, DMODEL, DMODEL);
}